// round 10
// baseline (speedup 1.0000x reference)
#include <cuda_runtime.h>
#include <cuda_fp16.h>

#define B_    16
#define A_    262144
#define G_    128
#define NTHR  256
#define NBLK  (A_ / NTHR)      /* 1024 */
#define NWARP (NTHR / 32)      /* 8 */

// fp16-packed pre-transformed gt: {half2(gcx,gcy), half2(log gw, log gh)} = 8B.
__device__ uint2    g_gth[B_ * G_];
// matched_idxs packed to int8, transposed to [A][16]: one uint4 per anchor.
__device__ uint4    g_m8[A_];
// Per-batch fg counts (int atomics -> deterministic) and weights 1/max(1,n).
__device__ int      g_cnt[B_];
__device__ float    g_w[B_];
// Per-block weighted partials.
__device__ float    g_bpart[NBLK];
__device__ unsigned g_done1 = 0;
__device__ unsigned g_done2 = 0;

// ---------------------------------------------------------------------------
// K1: read midx once -> (a) per-batch fg counts, (b) int8-packed transpose.
// Also pre-transforms gt into the fp16 table. Last block derives weights,
// resets state (graph-replay safe).
// ---------------------------------------------------------------------------
__global__ void __launch_bounds__(NTHR)
prep_kernel(const float4* __restrict__ gt, const int* __restrict__ midx)
{
    __shared__ int s_c[B_ * NWARP];
    __shared__ unsigned s_t;

    const int tid  = threadIdx.x;
    const int lane = tid & 31;
    const int warp = tid >> 5;
    const int a    = blockIdx.x * NTHR + tid;

    if (a < B_ * G_) {
        float4 g = gt[a];
        float gw = g.z - g.x;
        float gh = g.w - g.y;
        __half2 c = __floats2half2_rn(g.x + 0.5f * gw, g.y + 0.5f * gh);
        __half2 l = __floats2half2_rn(__logf(gw), __logf(gh));
        uint2 u;
        u.x = *reinterpret_cast<unsigned*>(&c);
        u.y = *reinterpret_cast<unsigned*>(&l);
        g_gth[a] = u;
    }

    uint4 pack;
    unsigned* pw = reinterpret_cast<unsigned*>(&pack);
#pragma unroll
    for (int b = 0; b < B_; b++) {
        int m = __ldcs(&midx[(size_t)b * A_ + a]);
        unsigned bal = __ballot_sync(0xffffffffu, m >= 0);
        if (lane == 0) s_c[b * NWARP + warp] = __popc(bal);
        unsigned byte = (unsigned)(m & 0xff) << (8 * (b & 3));
        if ((b & 3) == 0) pw[b >> 2]  = byte;
        else              pw[b >> 2] |= byte;
    }
    g_m8[a] = pack;    // coalesced 16B store

    __syncthreads();
    if (tid < B_) {
        int c = 0;
#pragma unroll
        for (int w = 0; w < NWARP; w++) c += s_c[tid * NWARP + w];
        atomicAdd(&g_cnt[tid], c);    // int add: order-independent
    }

    __threadfence();
    __syncthreads();
    if (tid == 0) s_t = atomicAdd(&g_done1, 1u);
    __syncthreads();

    if (s_t == (unsigned)(NBLK - 1)) {
        if (tid < B_) {
            int c = g_cnt[tid];
            g_w[tid]   = 1.0f / (float)(c > 1 ? c : 1);
            g_cnt[tid] = 0;
        }
        if (tid == 0) g_done1 = 0;
    }
}

// ---------------------------------------------------------------------------
// K2: weighted stream-accumulate. 1 uint4 index load + 16 pipelined bbox
// LDG.128 + 16 8-byte gathers per thread. No per-batch reduction in the loop.
// ---------------------------------------------------------------------------
__global__ void __launch_bounds__(NTHR, 6)
retina_loss_main(const float4* __restrict__ bbox,     // [B, A, 4]
                 const float4* __restrict__ anchors,  // [A, 4]
                 float*        __restrict__ out)
{
    __shared__ float s_w[B_];
    __shared__ float s_sum[NWARP];
    __shared__ unsigned s_t;

    const int tid  = threadIdx.x;
    const int lane = tid & 31;
    const int warp = tid >> 5;
    const int a    = blockIdx.x * NTHR + tid;   // NBLK*NTHR == A_

    if (tid < B_) s_w[tid] = g_w[tid];

    float4 an = __ldcs(&anchors[a]);
    float ex_w  = an.z - an.x;
    float ex_h  = an.w - an.y;
    float ex_cx = an.x + 0.5f * ex_w;
    float ex_cy = an.y + 0.5f * ex_h;
    float iw   = 1.0f / ex_w;
    float ih   = 1.0f / ex_h;
    float lexw = __logf(ex_w);
    float lexh = __logf(ex_h);

    // All 16 match indices in ONE 16-byte load.
    uint4 pack = __ldcs(&g_m8[a]);
    const unsigned* pw = reinterpret_cast<const unsigned*>(&pack);

    __syncthreads();   // s_w ready

    // 3-deep software pipeline on the bbox stream.
    float4 rbuf[3];
#pragma unroll
    for (int j = 0; j < 3; j++)
        rbuf[j] = __ldcs(&bbox[(size_t)j * A_ + a]);

    float s0 = 0.0f, s1 = 0.0f, s2 = 0.0f, s3 = 0.0f;

#pragma unroll
    for (int b = 0; b < B_; b++) {
        int mb = (int)(signed char)(pw[b >> 2] >> (8 * (b & 3)));
        const bool fg = (mb >= 0);

        float4 r = rbuf[b % 3];
        if (b + 3 < B_)
            rbuf[b % 3] = __ldcs(&bbox[(size_t)(b + 3) * A_ + a]);

        uint2 u = g_gth[b * G_ + (fg ? mb : 0)];   // 8-byte gather, L1-resident
        float2 cxy = __half22float2(*reinterpret_cast<__half2*>(&u.x));
        float2 lwh = __half22float2(*reinterpret_cast<__half2*>(&u.y));

        float dx = (cxy.x - ex_cx) * iw;
        float dy = (cxy.y - ex_cy) * ih;
        float dw = lwh.x - lexw;
        float dh = lwh.y - lexh;

        float l1 = fabsf(r.x - dx) + fabsf(r.y - dy)
                 + fabsf(r.z - dw) + fabsf(r.w - dh);
        float c  = fg ? s_w[b] * l1 : 0.0f;        // smem broadcast weight

        if      ((b & 3) == 0) s0 += c;
        else if ((b & 3) == 1) s1 += c;
        else if ((b & 3) == 2) s2 += c;
        else                   s3 += c;
    }

    float s = (s0 + s1) + (s2 + s3);

    // One warp reduce per thread for the whole kernel.
#pragma unroll
    for (int o = 16; o > 0; o >>= 1)
        s += __shfl_down_sync(0xffffffffu, s, o);
    if (lane == 0) s_sum[warp] = s;
    __syncthreads();

    if (tid == 0) {
        float bs = 0.0f;
#pragma unroll
        for (int w = 0; w < NWARP; w++) bs += s_sum[w];
        g_bpart[blockIdx.x] = bs;
    }

    // ---- last-block final fold (fixed order -> deterministic) ----
    __threadfence();
    __syncthreads();
    if (tid == 0) s_t = atomicAdd(&g_done2, 1u);
    __syncthreads();

    if (s_t == (unsigned)(NBLK - 1)) {
        float v = 0.0f;
#pragma unroll
        for (int i = 0; i < NBLK / NTHR; i++)
            v += __ldcg(&g_bpart[tid + i * NTHR]);
#pragma unroll
        for (int o = 16; o > 0; o >>= 1)
            v += __shfl_down_sync(0xffffffffu, v, o);
        if (lane == 0) s_sum[warp] = v;
        __syncthreads();
        if (tid == 0) {
            float tot = 0.0f;
#pragma unroll
            for (int w = 0; w < NWARP; w++) tot += s_sum[w];
            *out = tot * (1.0f / (float)B_);
            g_done2 = 0;
        }
    }
}

extern "C" void kernel_launch(void* const* d_in, const int* in_sizes, int n_in,
                              void* d_out, int out_size)
{
    const float4* bbox    = (const float4*)d_in[0];  // bbox_regression [B, A, 4] f32
    const float4* anchors = (const float4*)d_in[1];  // anchors [A, 4] f32
    const float4* gt      = (const float4*)d_in[2];  // gt_boxes [B, G, 4] f32
    const int*    midx    = (const int*)d_in[3];     // matched_idxs [B, A] i32

    prep_kernel<<<NBLK, NTHR>>>(gt, midx);
    retina_loss_main<<<NBLK, NTHR>>>(bbox, anchors, (float*)d_out);
}

// round 11
// speedup vs baseline: 1.0560x; 1.0560x over previous
#include <cuda_runtime.h>
#include <cuda_fp16.h>
#include <cstdint>

#define B_    16
#define A_    262144
#define G_    128
#define NTHR  256
#define NBLK  (A_ / NTHR)      /* 1024 */
#define NWARP (NTHR / 32)      /* 8 */
#define STAGES 4

// Pre-transformed gt table: {gcx, gcy, log(gw), log(gh)} per (b, g).
__device__ float4   g_gt[B_ * G_];
// Per-batch fg counts (int atomics -> deterministic) and weights 1/max(1,n).
__device__ int      g_cnt[B_];
__device__ float    g_w[B_];
// Per-block weighted partials.
__device__ float    g_bpart[NBLK];
__device__ unsigned g_done1 = 0;
__device__ unsigned g_done2 = 0;

// ---- minimal mbarrier / bulk-copy PTX ----
__device__ __forceinline__ uint32_t smem_u32(const void* p) {
    return (uint32_t)__cvta_generic_to_shared(p);
}
#define MBAR_INIT(addr, cnt) \
    asm volatile("mbarrier.init.shared.b64 [%0], %1;" :: "r"(addr), "r"(cnt) : "memory")
#define MBAR_EXPECT_TX(addr, bytes) \
    asm volatile("mbarrier.arrive.expect_tx.shared.b64 _, [%0], %1;" :: "r"(addr), "r"(bytes) : "memory")
#define MBAR_WAIT(addr, phase) do {                                           \
    unsigned _done = 0;                                                       \
    while (!_done) {                                                          \
        asm volatile("{\n\t.reg .pred p;\n\t"                                 \
            "mbarrier.try_wait.parity.acquire.cta.shared::cta.b64 p, [%1], %2;\n\t" \
            "selp.b32 %0, 1, 0, p;\n\t}"                                      \
            : "=r"(_done) : "r"(addr), "r"(phase) : "memory");                \
    } } while (0)
#define BULK_G2S(dst, src, bytes, mbar) \
    asm volatile("cp.async.bulk.shared::cluster.global.mbarrier::complete_tx::bytes " \
                 "[%0], [%1], %2, [%3];"                                      \
                 :: "r"(dst), "l"(src), "r"(bytes), "r"(mbar) : "memory")

// ---------------------------------------------------------------------------
// K1 (identical to R8's proven prep): fg counts + gt pre-transform.
// ---------------------------------------------------------------------------
__global__ void __launch_bounds__(NTHR)
prep_kernel(const float4* __restrict__ gt, const int* __restrict__ midx)
{
    __shared__ int s_c[B_ * NWARP];
    __shared__ unsigned s_t;

    const int tid  = threadIdx.x;
    const int lane = tid & 31;
    const int warp = tid >> 5;
    const int a    = blockIdx.x * NTHR + tid;

    if (a < B_ * G_) {
        float4 g = gt[a];
        float gw = g.z - g.x;
        float gh = g.w - g.y;
        g_gt[a] = make_float4(g.x + 0.5f * gw, g.y + 0.5f * gh,
                              __logf(gw), __logf(gh));
    }

#pragma unroll
    for (int b = 0; b < B_; b++) {
        int m = __ldcs(&midx[(size_t)b * A_ + a]);
        unsigned bal = __ballot_sync(0xffffffffu, m >= 0);
        if (lane == 0) s_c[b * NWARP + warp] = __popc(bal);
    }
    __syncthreads();

    if (tid < B_) {
        int c = 0;
#pragma unroll
        for (int w = 0; w < NWARP; w++) c += s_c[tid * NWARP + w];
        atomicAdd(&g_cnt[tid], c);
    }

    __threadfence();
    __syncthreads();
    if (tid == 0) s_t = atomicAdd(&g_done1, 1u);
    __syncthreads();

    if (s_t == (unsigned)(NBLK - 1)) {
        if (tid < B_) {
            int c = g_cnt[tid];
            g_w[tid]   = 1.0f / (float)(c > 1 ? c : 1);
            g_cnt[tid] = 0;
        }
        if (tid == 0) g_done1 = 0;
    }
}

// ---------------------------------------------------------------------------
// K2: bbox stream moved OFF the warp scoreboards onto cp.async.bulk.
// 4-stage smem ring (4 KB/stage), one producer thread, mbarrier complete_tx.
// gt gather in L1, weighted single-accumulator hot loop (R8 algebra).
// ---------------------------------------------------------------------------
__global__ void __launch_bounds__(NTHR)
retina_loss_main(const float4* __restrict__ bbox,     // [B, A, 4]
                 const float4* __restrict__ anchors,  // [A, 4]
                 const int*    __restrict__ midx,     // [B, A]
                 float*        __restrict__ out)
{
    __shared__ float4   s_box[STAGES][NTHR];   // 16 KB ring
    __shared__ uint64_t s_mbar[STAGES];
    __shared__ float    s_w[B_];
    __shared__ float    s_sum[NWARP];
    __shared__ unsigned s_t;

    const int tid  = threadIdx.x;
    const int lane = tid & 31;
    const int warp = tid >> 5;
    const int a    = blockIdx.x * NTHR + tid;   // NBLK*NTHR == A_

    if (tid < B_) s_w[tid] = g_w[tid];
    if (tid == 0) {
#pragma unroll
        for (int s = 0; s < STAGES; s++)
            MBAR_INIT(smem_u32(&s_mbar[s]), 1);
    }
    __syncthreads();

    // Kick off the first STAGES bulk copies (4 KB contiguous each).
    const float4* blk_base = bbox + (size_t)blockIdx.x * NTHR;
    if (tid == 0) {
#pragma unroll
        for (int s = 0; s < STAGES; s++) {
            uint32_t mb = smem_u32(&s_mbar[s]);
            MBAR_EXPECT_TX(mb, NTHR * 16);
            BULK_G2S(smem_u32(&s_box[s][0]),
                     (const void*)(blk_base + (size_t)s * A_),
                     NTHR * 16, mb);
        }
    }

    // Anchor-derived constants (loaded once).
    float4 an = __ldcs(&anchors[a]);
    float ex_w  = an.z - an.x;
    float ex_h  = an.w - an.y;
    float ex_cx = an.x + 0.5f * ex_w;
    float ex_cy = an.y + 0.5f * ex_h;
    float iw   = 1.0f / ex_w;
    float ih   = 1.0f / ex_h;
    float lexw = __logf(ex_w);
    float lexh = __logf(ex_h);

    // Front-batch all 16 matched-index loads (coalesced, high MLP).
    int m[B_];
#pragma unroll
    for (int b = 0; b < B_; b++)
        m[b] = __ldcs(&midx[(size_t)b * A_ + a]);

    float s0 = 0.0f, s1 = 0.0f, s2 = 0.0f, s3 = 0.0f;

#pragma unroll
    for (int b = 0; b < B_; b++) {
        const int st = b & (STAGES - 1);
        MBAR_WAIT(smem_u32(&s_mbar[st]), (b >> 2) & 1);

        float4 r = s_box[st][tid];             // LDS.128, conflict-free
        const bool fg = (m[b] >= 0);
        float4 t = g_gt[b * G_ + (fg ? m[b] : 0)];   // 32 KB table, L1-hot

        float dx = (t.x - ex_cx) * iw;
        float dy = (t.y - ex_cy) * ih;
        float dw = t.z - lexw;
        float dh = t.w - lexh;

        float l1 = fabsf(r.x - dx) + fabsf(r.y - dy)
                 + fabsf(r.z - dw) + fabsf(r.w - dh);
        float c  = fg ? s_w[b] * l1 : 0.0f;

        if      ((b & 3) == 0) s0 += c;
        else if ((b & 3) == 1) s1 += c;
        else if ((b & 3) == 2) s2 += c;
        else                   s3 += c;

        // All threads done with stage st -> safe to refill it.
        __syncthreads();
        if (tid == 0 && b + STAGES < B_) {
            uint32_t mb = smem_u32(&s_mbar[st]);
            MBAR_EXPECT_TX(mb, NTHR * 16);
            BULK_G2S(smem_u32(&s_box[st][0]),
                     (const void*)(blk_base + (size_t)(b + STAGES) * A_),
                     NTHR * 16, mb);
        }
    }

    float s = (s0 + s1) + (s2 + s3);

    // One warp reduce per thread for the whole kernel.
#pragma unroll
    for (int o = 16; o > 0; o >>= 1)
        s += __shfl_down_sync(0xffffffffu, s, o);
    if (lane == 0) s_sum[warp] = s;
    __syncthreads();

    if (tid == 0) {
        float bs = 0.0f;
#pragma unroll
        for (int w = 0; w < NWARP; w++) bs += s_sum[w];
        g_bpart[blockIdx.x] = bs;
    }

    // ---- last-block final fold (fixed order -> deterministic) ----
    __threadfence();
    __syncthreads();
    if (tid == 0) s_t = atomicAdd(&g_done2, 1u);
    __syncthreads();

    if (s_t == (unsigned)(NBLK - 1)) {
        float v = 0.0f;
#pragma unroll
        for (int i = 0; i < NBLK / NTHR; i++)
            v += __ldcg(&g_bpart[tid + i * NTHR]);
#pragma unroll
        for (int o = 16; o > 0; o >>= 1)
            v += __shfl_down_sync(0xffffffffu, v, o);
        if (lane == 0) s_sum[warp] = v;
        __syncthreads();
        if (tid == 0) {
            float tot = 0.0f;
#pragma unroll
            for (int w = 0; w < NWARP; w++) tot += s_sum[w];
            *out = tot * (1.0f / (float)B_);
            g_done2 = 0;
        }
    }
}

extern "C" void kernel_launch(void* const* d_in, const int* in_sizes, int n_in,
                              void* d_out, int out_size)
{
    const float4* bbox    = (const float4*)d_in[0];  // bbox_regression [B, A, 4] f32
    const float4* anchors = (const float4*)d_in[1];  // anchors [A, 4] f32
    const float4* gt      = (const float4*)d_in[2];  // gt_boxes [B, G, 4] f32
    const int*    midx    = (const int*)d_in[3];     // matched_idxs [B, A] i32

    prep_kernel<<<NBLK, NTHR>>>(gt, midx);
    retina_loss_main<<<NBLK, NTHR>>>(bbox, anchors, midx, (float*)d_out);
}

// round 12
// speedup vs baseline: 1.1150x; 1.0559x over previous
#include <cuda_runtime.h>
#include <cuda_fp16.h>

#define B_    16
#define A_    262144
#define G_    128
#define NTHR  256
#define NBLK  (A_ / NTHR)      /* 1024 */
#define NWARP (NTHR / 32)      /* 8 */

// Pre-transformed gt table: {gcx, gcy, log(gw), log(gh)} per (b, g).
__device__ float4   g_gt[B_ * G_];
// int8 shadow of matched_idxs (values fit in [-2, 127]): 4.2 MB vs 16.8 MB.
__device__ signed char g_m8[B_ * A_];
// Per-batch fg counts (int atomics -> deterministic) and weights 1/max(1,n).
__device__ int      g_cnt[B_];
__device__ float    g_w[B_];
// Per-block weighted partials.
__device__ float    g_bpart[NBLK];
__device__ unsigned g_done1 = 0;
__device__ unsigned g_done2 = 0;

// ---------------------------------------------------------------------------
// K1: read midx once -> fg counts + int8 shadow copy. Pre-transform gt.
// Last block derives weights and resets state (graph-replay safe).
// ---------------------------------------------------------------------------
__global__ void __launch_bounds__(NTHR)
prep_kernel(const float4* __restrict__ gt, const int* __restrict__ midx)
{
    __shared__ int s_c[B_ * NWARP];
    __shared__ unsigned s_t;

    const int tid  = threadIdx.x;
    const int lane = tid & 31;
    const int warp = tid >> 5;
    const int a    = blockIdx.x * NTHR + tid;

    if (a < B_ * G_) {
        float4 g = gt[a];
        float gw = g.z - g.x;
        float gh = g.w - g.y;
        g_gt[a] = make_float4(g.x + 0.5f * gw, g.y + 0.5f * gh,
                              __logf(gw), __logf(gh));
    }

#pragma unroll
    for (int b = 0; b < B_; b++) {
        int m = __ldcs(&midx[(size_t)b * A_ + a]);
        unsigned bal = __ballot_sync(0xffffffffu, m >= 0);
        if (lane == 0) s_c[b * NWARP + warp] = __popc(bal);
        g_m8[(size_t)b * A_ + a] = (signed char)m;   // coalesced byte store
    }
    __syncthreads();

    if (tid < B_) {
        int c = 0;
#pragma unroll
        for (int w = 0; w < NWARP; w++) c += s_c[tid * NWARP + w];
        atomicAdd(&g_cnt[tid], c);    // int add: order-independent
    }

    __threadfence();
    __syncthreads();
    if (tid == 0) s_t = atomicAdd(&g_done1, 1u);
    __syncthreads();

    if (s_t == (unsigned)(NBLK - 1)) {
        if (tid < B_) {
            int c = g_cnt[tid];
            g_w[tid]   = 1.0f / (float)(c > 1 ? c : 1);
            g_cnt[tid] = 0;
        }
        if (tid == 0) g_done1 = 0;
    }
}

// ---------------------------------------------------------------------------
// K2: R8's proven weighted stream-accumulate, with (i) int8 midx (4.2 MB),
// (ii) weights via one-time smem broadcast. Otherwise byte-identical to R8.
// ---------------------------------------------------------------------------
__global__ void __launch_bounds__(NTHR, 7)
retina_loss_main(const float4* __restrict__ bbox,     // [B, A, 4]
                 const float4* __restrict__ anchors,  // [A, 4]
                 float*        __restrict__ out)
{
    __shared__ float s_w[B_];
    __shared__ float s_sum[NWARP];
    __shared__ unsigned s_t;

    const int tid  = threadIdx.x;
    const int lane = tid & 31;
    const int warp = tid >> 5;
    const int a    = blockIdx.x * NTHR + tid;   // NBLK*NTHR == A_

    if (tid < B_) s_w[tid] = g_w[tid];

    // Anchor loaded ONCE, reused for all 16 batches.
    float4 an = __ldcs(&anchors[a]);
    float ex_w  = an.z - an.x;
    float ex_h  = an.w - an.y;
    float ex_cx = an.x + 0.5f * ex_w;
    float ex_cy = an.y + 0.5f * ex_h;
    float iw   = 1.0f / ex_w;
    float ih   = 1.0f / ex_h;
    float lexw = __logf(ex_w);
    float lexh = __logf(ex_h);

    // Front-batch all 16 matched-index byte loads (coalesced, 1 sector/warp).
    int m[B_];
#pragma unroll
    for (int b = 0; b < B_; b++)
        m[b] = (int)__ldcs(&g_m8[(size_t)b * A_ + a]);

    __syncthreads();   // s_w ready

    float s0 = 0.0f, s1 = 0.0f, s2 = 0.0f, s3 = 0.0f;

#pragma unroll
    for (int b = 0; b < B_; b++) {
        const bool fg = (m[b] >= 0);
        float4 r = __ldcs(&bbox[(size_t)b * A_ + a]);
        float4 t = g_gt[b * G_ + (fg ? m[b] : 0)];  // 32 KB table, L1-resident

        float dx = (t.x - ex_cx) * iw;
        float dy = (t.y - ex_cy) * ih;
        float dw = t.z - lexw;     // log(gw) - log(ex_w)
        float dh = t.w - lexh;

        float l1 = fabsf(r.x - dx) + fabsf(r.y - dy)
                 + fabsf(r.z - dw) + fabsf(r.w - dh);
        float c  = fg ? s_w[b] * l1 : 0.0f;

        // 4 rotating accumulators: dependency chain length B_/4.
        if      ((b & 3) == 0) s0 += c;
        else if ((b & 3) == 1) s1 += c;
        else if ((b & 3) == 2) s2 += c;
        else                   s3 += c;
    }

    float s = (s0 + s1) + (s2 + s3);

    // ONE warp reduce for the whole thread.
#pragma unroll
    for (int o = 16; o > 0; o >>= 1)
        s += __shfl_down_sync(0xffffffffu, s, o);
    if (lane == 0) s_sum[warp] = s;
    __syncthreads();

    if (tid == 0) {
        float bs = 0.0f;
#pragma unroll
        for (int w = 0; w < NWARP; w++) bs += s_sum[w];
        g_bpart[blockIdx.x] = bs;
    }

    // ---- last-block final fold (fixed order -> deterministic) ----
    __threadfence();
    __syncthreads();
    if (tid == 0) s_t = atomicAdd(&g_done2, 1u);
    __syncthreads();

    if (s_t == (unsigned)(NBLK - 1)) {
        float v = 0.0f;
#pragma unroll
        for (int i = 0; i < NBLK / NTHR; i++)
            v += __ldcg(&g_bpart[tid + i * NTHR]);
#pragma unroll
        for (int o = 16; o > 0; o >>= 1)
            v += __shfl_down_sync(0xffffffffu, v, o);
        if (lane == 0) s_sum[warp] = v;
        __syncthreads();
        if (tid == 0) {
            float tot = 0.0f;
#pragma unroll
            for (int w = 0; w < NWARP; w++) tot += s_sum[w];
            *out = tot * (1.0f / (float)B_);
            g_done2 = 0;
        }
    }
}

extern "C" void kernel_launch(void* const* d_in, const int* in_sizes, int n_in,
                              void* d_out, int out_size)
{
    const float4* bbox    = (const float4*)d_in[0];  // bbox_regression [B, A, 4] f32
    const float4* anchors = (const float4*)d_in[1];  // anchors [A, 4] f32
    const float4* gt      = (const float4*)d_in[2];  // gt_boxes [B, G, 4] f32
    const int*    midx    = (const int*)d_in[3];     // matched_idxs [B, A] i32

    prep_kernel<<<NBLK, NTHR>>>(gt, midx);
    retina_loss_main<<<NBLK, NTHR>>>(bbox, anchors, (float*)d_out);
}